// round 11
// baseline (speedup 1.0000x reference)
#include <cuda_runtime.h>
#include <cuda_bf16.h>
#include <math_constants.h>

#define W      384
#define H      384
#define WV     96     // W / 4 float4 lanes per row
#define RPT    16     // rows per thread strip
#define STRIPS (H / RPT)          // 24
#define SPB    4                  // strips per block
// sigmoid(x) > 0.05  <=>  x > ln(0.05/0.95)
#define THRESH_X (-2.9444389791664403f)

struct RowLd { float4 v; float lo; float hi; };

// Load one row: the owned float4 always; scalar halo loads ONLY for warp-seam
// lanes (lane 0 / lane 31) — interior lanes get halos via shuffle at consume.
__device__ __forceinline__ RowLd load_row(const float* __restrict__ plane,
                                          int q, int t, int lane) {
    RowLd r;
    r.lo = -CUDART_INF_F;
    r.hi = -CUDART_INF_F;
    if ((unsigned)q < (unsigned)H) {
        const float* rowbase = plane + (size_t)q * W;
        r.v = *reinterpret_cast<const float4*>(rowbase + 4 * t);
        if (lane == 0 && t > 0)       r.lo = __ldg(rowbase + 4 * t - 1);
        if (lane == 31 && t < WV - 1) r.hi = __ldg(rowbase + 4 * t + 4);
    } else {
        r.v = make_float4(-CUDART_INF_F, -CUDART_INF_F,
                          -CUDART_INF_F, -CUDART_INF_F);
    }
    return r;
}

// Horizontal 3-max per lane; cross-lane halos via warp shuffle, warp-seam
// lanes fall back to the scalar values fetched at load time.
__device__ __forceinline__ float4 hmax(const RowLd& a, int lane) {
    float lo_s = __shfl_up_sync(0xffffffffu, a.v.w, 1);
    float hi_s = __shfl_down_sync(0xffffffffu, a.v.x, 1);
    float lo = (lane == 0)  ? a.lo : lo_s;
    float hi = (lane == 31) ? a.hi : hi_s;
    float4 h;
    h.x = fmaxf(lo,    fmaxf(a.v.x, a.v.y));
    h.y = fmaxf(a.v.x, fmaxf(a.v.y, a.v.z));
    h.z = fmaxf(a.v.y, fmaxf(a.v.z, a.v.w));
    h.w = fmaxf(a.v.z, fmaxf(a.v.w, hi));
    return h;
}

__device__ __forceinline__ float sigmoidf_fast(float x) {
    return 1.0f / (1.0f + __expf(-x));
}

__device__ __forceinline__ float peak_out(float v, float hp, float hc, float hn) {
    float m = fmaxf(hp, fmaxf(hc, hn));     // 3x3 max; hc already includes v
    return (v == m && v > THRESH_X) ? sigmoidf_fast(v) : 0.0f;
}

__global__ __launch_bounds__(WV * SPB, 4)
void heatmap_peaks_kernel(const float* __restrict__ in, float* __restrict__ out) {
    const int t     = threadIdx.x;                           // 0..95
    const int lane  = t & 31;
    const int strip = blockIdx.x * SPB + threadIdx.y;        // 0..23
    const int p     = blockIdx.y;                            // plane 0..271

    const float* plane  = in  + (size_t)p * (W * H);
    float*       oplane = out + (size_t)p * (W * H);
    const int r0 = strip * RPT;

    // Prologue: rows r0-1 .. r0+2 issued back-to-back (all independent).
    RowLd A = load_row(plane, r0 - 1, t, lane);
    RowLd B = load_row(plane, r0,     t, lane);
    RowLd C = load_row(plane, r0 + 1, t, lane);   // consumed at i=0
    RowLd D = load_row(plane, r0 + 2, t, lane);   // consumed at i=1

    float4 hprev = hmax(A, lane);
    float4 hcur  = hmax(B, lane);
    float4 vcur  = B.v;

    float* orow = oplane + (size_t)r0 * W + 4 * t;

    #pragma unroll
    for (int i = 0; i < RPT; ++i) {
        // Issue row r+3 first: two rows (D, E) stay in flight while we
        // consume C, which was loaded two iterations before.
        RowLd E = load_row(plane, r0 + i + 3, t, lane);

        float4 hnext = hmax(C, lane);
        float4 vnext = C.v;

        float4 o;
        o.x = peak_out(vcur.x, hprev.x, hcur.x, hnext.x);
        o.y = peak_out(vcur.y, hprev.y, hcur.y, hnext.y);
        o.z = peak_out(vcur.z, hprev.z, hcur.z, hnext.z);
        o.w = peak_out(vcur.w, hprev.w, hcur.w, hnext.w);

        __stcs(reinterpret_cast<float4*>(orow), o);   // streaming store
        orow += W;

        hprev = hcur;
        hcur  = hnext;
        vcur  = vnext;
        C     = D;
        D     = E;
    }
}

extern "C" void kernel_launch(void* const* d_in, const int* in_sizes, int n_in,
                              void* d_out, int out_size) {
    (void)in_sizes; (void)n_in; (void)out_size;
    const float* in = (const float*)d_in[0];
    float* out = (float*)d_out;

    dim3 block(WV, SPB);                      // 96 x 4 = 384 threads
    dim3 grid(STRIPS / SPB, 16 * 17);         // (6, 272) = 1632 CTAs
    heatmap_peaks_kernel<<<grid, block>>>(in, out);
}

// round 14
// speedup vs baseline: 1.2090x; 1.2090x over previous
#include <cuda_runtime.h>
#include <cuda_bf16.h>
#include <math_constants.h>
#include <cstdint>

#define W      384
#define H      384
#define WV     96                 // W/4 float4 lanes per row
#define RPT    16                 // rows per strip
#define STRIPS (H / RPT)          // 24
#define DPTH   6                  // smem ring depth (rows)
#define LEAD   3                  // prefetch lead (rows in flight)
// sigmoid(x) > 0.05  <=>  x > ln(0.05/0.95)
#define THRESH_X (-2.9444389791664403f)

__device__ __forceinline__ void cp_async16(unsigned int smem_addr,
                                           const void* gptr) {
    asm volatile("cp.async.cg.shared.global [%0], [%1], 16;\n"
                 :: "r"(smem_addr), "l"(gptr));
}
__device__ __forceinline__ void cp_commit() {
    asm volatile("cp.async.commit_group;\n");
}
template <int N>
__device__ __forceinline__ void cp_wait() {
    asm volatile("cp.async.wait_group %0;\n" :: "n"(N));
}

__device__ __forceinline__ float sigmoidf_fast(float x) {
    return 1.0f / (1.0f + __expf(-x));
}

__device__ __forceinline__ float peak_out(float v, float hp, float hc, float hn) {
    float m = fmaxf(hp, fmaxf(hc, hn));     // 3x3 max; hc already includes v
    return (v == m && v > THRESH_X) ? sigmoidf_fast(v) : 0.0f;
}

// Read logical row j from the ring: owned float4 + clamped halo scalars,
// return horizontal 3-max (center values via *val_out).
// Clamped indices duplicate in-window elements, which leaves the max
// unchanged — exactly equivalent to -inf SAME padding for the peak test.
__device__ __forceinline__ float4 read_hmax(const float (*ring)[W], int j, int t,
                                            float4* val_out) {
    const float* row = ring[j % DPTH];
    float4 v = *reinterpret_cast<const float4*>(row + 4 * t);
    float lo = row[max(4 * t - 1, 0)];
    float hi = row[min(4 * t + 4, W - 1)];
    *val_out = v;
    float4 h;
    h.x = fmaxf(lo,  fmaxf(v.x, v.y));
    h.y = fmaxf(v.x, fmaxf(v.y, v.z));
    h.z = fmaxf(v.y, fmaxf(v.z, v.w));
    h.w = fmaxf(v.z, fmaxf(v.w, hi));
    return h;
}

__global__ __launch_bounds__(WV)
void heatmap_peaks_kernel(const float* __restrict__ in, float* __restrict__ out) {
    __shared__ float ring[DPTH][W];                 // 9216 B

    const int t     = threadIdx.x;                  // 0..95
    const int strip = blockIdx.x;                   // 0..23
    const int p     = blockIdx.y;                   // plane 0..271

    const float* plane  = in  + (size_t)p * (W * H);
    float*       oplane = out + (size_t)p * (W * H);
    const int r0 = strip * RPT;

    const unsigned int ring_base =
        (unsigned int)__cvta_generic_to_shared(&ring[0][0]);

    // Issue logical row j (j=0 is r0-1). Row index clamped to [0, H-1]:
    // duplicating an in-window row leaves the 3x3 max unchanged.
    auto issue = [&](int j) {
        int gr = r0 - 1 + j;
        gr = max(0, min(H - 1, gr));
        const float* src = plane + (size_t)gr * W + 4 * t;
        unsigned int dst =
            ring_base + (unsigned int)(((j % DPTH) * W + 4 * t) * 4);
        cp_async16(dst, src);
        cp_commit();
    };

    // Prologue: groups #1..#5 carry rows j = 0..4 (group #k = row k-1).
    #pragma unroll
    for (int j = 0; j <= LEAD + 1; ++j) issue(j);

    // Rows j=0,1 complete: allow newest 3 groups pending.
    cp_wait<3>();
    __syncthreads();

    float4 vtmp, vcur;
    float4 hprev = read_hmax(ring, 0, t, &vtmp);
    float4 hcur  = read_hmax(ring, 1, t, &vcur);

    float* orow = oplane + (size_t)r0 * W + 4 * t;

    #pragma unroll
    for (int i = 0; i < RPT; ++i) {
        // Groups issued so far: #1..#(5+i) (one per prior iteration, empty
        // ones at the tail). wait<2> completes #1..#(i+3); group #(i+3)
        // holds row i+2 — exactly the row consumed below. Tail-safe because
        // every iteration commits a group, even when nothing is issued.
        cp_wait<LEAD - 1>();
        __syncthreads();   // publish cp.async data + guard slot reuse

        float4 vnext;
        float4 hnext = read_hmax(ring, i + 2, t, &vnext);

        // Refill: row j = i + LEAD + 2 into slot (i-1)%DPTH (last read at
        // iteration i-3 — barrier-safe). Past the end, commit an EMPTY
        // group to keep the wait_group arithmetic exact.
        int jn = i + LEAD + 2;
        if (jn <= RPT + 1) {
            issue(jn);
        } else {
            cp_commit();
        }

        float4 o;
        o.x = peak_out(vcur.x, hprev.x, hcur.x, hnext.x);
        o.y = peak_out(vcur.y, hprev.y, hcur.y, hnext.y);
        o.z = peak_out(vcur.z, hprev.z, hcur.z, hnext.z);
        o.w = peak_out(vcur.w, hprev.w, hcur.w, hnext.w);

        __stcs(reinterpret_cast<float4*>(orow), o);   // streaming store
        orow += W;

        hprev = hcur;
        hcur  = hnext;
        vcur  = vnext;
    }
}

extern "C" void kernel_launch(void* const* d_in, const int* in_sizes, int n_in,
                              void* d_out, int out_size) {
    (void)in_sizes; (void)n_in; (void)out_size;
    const float* in = (const float*)d_in[0];
    float* out = (float*)d_out;

    dim3 block(WV, 1);                 // 96 threads (3 warps)
    dim3 grid(STRIPS, 16 * 17);        // (24, 272) = 6528 CTAs
    heatmap_peaks_kernel<<<grid, block>>>(in, out);
}